// round 1
// baseline (speedup 1.0000x reference)
#include <cuda_runtime.h>

typedef unsigned long long ULL;

// ---------------- constants ----------------
constexpr int B  = 4;
constexpr int C  = 64;
constexpr int H  = 128;
constexpr int W  = 128;
constexpr int Hp = 130;
constexpr int Wp = 130;
constexpr int O  = 64;
constexpr int N9 = 9;

// ---------------- scratch (device globals; no allocs) ----------------
__device__ __align__(16) float g_xpad[B * Hp * Wp * C];   // NHWC zero-padded x0 (~17.3 MB)
__device__ __align__(16) float g_wT[C * N9 * O];          // conv_w transposed: [c][n][o]
__device__ __align__(16) ULL   g_pw2[N9 * C * N9];        // paired offset-conv weights: [n][c][kk] -> (w_x, w_y)
__device__ __align__(16) int4   g_midx[B * H * W * N9];   // 4 corner element-offsets into g_xpad
__device__ __align__(16) float4 g_mw[B * H * W * N9];     // 4 bilinear weights (lt, rb, lb, rt)

// ---------------- packed f32x2 helpers ----------------
__device__ __forceinline__ ULL ffma2(ULL a, ULL b, ULL c) {
    ULL d;
    asm("fma.rn.f32x2 %0, %1, %2, %3;" : "=l"(d) : "l"(a), "l"(b), "l"(c));
    return d;
}
__device__ __forceinline__ ULL pack2(float lo, float hi) {
    ULL d;
    asm("mov.b64 %0, {%1, %2};" : "=l"(d) : "f"(lo), "f"(hi));
    return d;
}
__device__ __forceinline__ void unpack2(ULL v, float& lo, float& hi) {
    asm("mov.b64 {%0, %1}, %2;" : "=f"(lo), "=f"(hi) : "l"(v));
}

// ============================================================================
// K1: pad + NCHW->NHWC transpose of x0 into g_xpad.
// Block: 256 threads, handles 32 padded-pixel positions x 64 channels.
// ============================================================================
__global__ void __launch_bounds__(256) k_pad_transpose(const float* __restrict__ x0) {
    __shared__ float tile[64][33];
    int bp = blockIdx.x;                 // B * 529 blocks
    int b  = bp / 529;
    int p0 = (bp - b * 529) * 32;
    int tx = threadIdx.x & 31;
    int ty = threadIdx.x >> 5;

    #pragma unroll
    for (int cc = ty; cc < 64; cc += 8) {
        int p = p0 + tx;
        float v = 0.f;
        if (p < Hp * Wp) {
            int y = p / Wp, x = p - (p / Wp) * Wp;
            if (y >= 1 && y <= H && x >= 1 && x <= W)
                v = x0[((b * C + cc) * H + (y - 1)) * W + (x - 1)];
        }
        tile[cc][tx] = v;
    }
    __syncthreads();

    int base = (b * Hp * Wp + p0) * 64;
    for (int e = threadIdx.x; e < 32 * 64; e += 256) {
        int pl = e >> 6, c = e & 63;
        if (p0 + pl < Hp * Wp)
            g_xpad[base + pl * 64 + c] = tile[c][pl];
    }
}

// ============================================================================
// K1b: weight reshuffles.
//   g_wT[c][n][o]      = conv_w[o][c][n]
//   g_pw2[n][c][kk]    = pair( p_w[n][c][kk], p_w[n+9][c][kk] )
// ============================================================================
__global__ void k_prep_w(const float* __restrict__ conv_w, const float* __restrict__ p_w) {
    int t = blockIdx.x * 256 + threadIdx.x;
    if (t < O * C * N9) {
        int o = t / (C * N9);
        int c = (t / N9) % C;
        int n = t % N9;
        g_wT[(c * N9 + n) * O + o] = conv_w[t];
    }
    if (t < N9 * C * N9) {
        int n = t / (C * N9);
        int c = (t / N9) % C;
        int kk = t % N9;
        float wx = p_w[(n * C + c) * N9 + kk];
        float wy = p_w[((n + 9) * C + c) * N9 + kk];
        g_pw2[(n * C + c) * N9 + kk] = pack2(wx, wy);
    }
}

// ============================================================================
// K2: offset conv (3x3, pad 1, 18 out channels) fused with bilinear metadata.
// One thread per output pixel. (off_x, off_y) pairs accumulated as f32x2.
// ============================================================================
__global__ void __launch_bounds__(256) k_offset_meta(const float* __restrict__ x1,
                                                     const float* __restrict__ p_b) {
    __shared__ ULL wsm[N9 * C * N9];   // 41472 bytes
    int t = threadIdx.x;
    for (int k = t; k < N9 * C * N9; k += 256) wsm[k] = g_pw2[k];
    __syncthreads();

    int P = blockIdx.x * 256 + t;          // 65536 pixels
    int b = P >> 14;
    int rem = P & 16383;
    int i = rem >> 7;
    int j = rem & 127;

    ULL acc[9];
    #pragma unroll
    for (int n = 0; n < 9; n++) acc[n] = pack2(p_b[n], p_b[n + 9]);

    const float* x1b = x1 + (b * C * H * W) + i * W + j;
    bool rok0 = (i > 0), rok2 = (i < H - 1), cok0 = (j > 0), cok2 = (j < W - 1);

    #pragma unroll 1
    for (int c = 0; c < C; c++) {
        const float* xc = x1b + c * (H * W);
        float v[9];
        #pragma unroll
        for (int di = 0; di < 3; di++) {
            bool rok = (di == 0) ? rok0 : ((di == 2) ? rok2 : true);
            const float* xr = xc + (di - 1) * W;
            v[di * 3 + 0] = (rok && cok0) ? xr[-1] : 0.f;
            v[di * 3 + 1] = rok ? xr[0] : 0.f;
            v[di * 3 + 2] = (rok && cok2) ? xr[1] : 0.f;
        }
        ULL vd[9];
        #pragma unroll
        for (int k = 0; k < 9; k++) vd[k] = pack2(v[k], v[k]);
        const ULL* wrow = &wsm[c * N9];
        #pragma unroll
        for (int n = 0; n < 9; n++) {
            const ULL* wn = wrow + n * (C * N9);
            #pragma unroll
            for (int k = 0; k < 9; k++)
                acc[n] = ffma2(vd[k], wn[k], acc[n]);
        }
    }

    // bilinear metadata (replicates the reference clipping exactly)
    int gs = P * 9;
    int xb130 = b * 130;
    #pragma unroll
    for (int n = 0; n < 9; n++) {
        float ox, oy;
        unpack2(acc[n], ox, oy);
        float px = (float)(i + n / 3) + ox;      // (i+1) + (n/3 - 1) + off_x
        float py = (float)(j + n % 3) + oy;      // (j+1) + (n%3 - 1) + off_y
        float fx = floorf(px), fy = floorf(py);
        int qltx = max(min((int)fx, Hp - 1), 0);
        int qlty = max(min((int)fy, Wp - 1), 0);
        int qrbx = max(min((int)fx + 1, Hp - 1), 0);
        int qrby = max(min((int)fy + 1, Wp - 1), 0);
        float pxc = fminf(fmaxf(px, 0.f), (float)(Hp - 1));
        float pyc = fminf(fmaxf(py, 0.f), (float)(Wp - 1));
        float ax = 1.f + (float)qltx - pxc;
        float bx = 1.f - (float)qrbx + pxc;
        float ay = 1.f + (float)qlty - pyc;
        float by = 1.f - (float)qrby + pyc;
        int4 idx;
        idx.x = ((xb130 + qltx) * 130 + qlty) * 64;   // lt
        idx.y = ((xb130 + qrbx) * 130 + qrby) * 64;   // rb
        idx.z = ((xb130 + qltx) * 130 + qrby) * 64;   // lb
        idx.w = ((xb130 + qrbx) * 130 + qlty) * 64;   // rt
        float4 wv;
        wv.x = ax * ay;  // g_lt
        wv.y = bx * by;  // g_rb
        wv.z = ax * by;  // g_lb
        wv.w = bx * ay;  // g_rt
        g_midx[gs + n] = idx;
        g_mw[gs + n] = wv;
    }
}

// ============================================================================
// K3: gather + reduction GEMM.
// Block = (b, row i, half-row jt): 64 pixels x 64 out-channels.
// 16 chunks of 4 input channels: gather xoff into smem (NHWC float4 loads),
// then a 4o x 4pix register-blocked GEMM with f32x2 (pixel pairs packed).
// ============================================================================
__global__ void __launch_bounds__(256) k_main(float* __restrict__ out) {
    __shared__ int4   smidx[576];
    __shared__ float4 smw[576];
    __shared__ float  xoffs[4 * 9 * 64];   // [cc][n][pix]
    __shared__ float  ws[4 * 9 * 64];      // [cc][n][o]

    int t = threadIdx.x;
    int bid = blockIdx.x;                  // 1024 blocks
    int jt = bid & 1;
    int i  = (bid >> 1) & 127;
    int b  = bid >> 8;
    int pixbase = ((b * H + i) * W + jt * 64);

    for (int s = t; s < 576; s += 256) {
        smidx[s] = g_midx[pixbase * 9 + s];
        smw[s]   = g_mw[pixbase * 9 + s];
    }

    int pg = t & 15, og = t >> 4;
    int pix0 = pg * 4, o0 = og * 4;
    ULL acc[4][2];
    #pragma unroll
    for (int k = 0; k < 4; k++) { acc[k][0] = 0ull; acc[k][1] = 0ull; }

    __syncthreads();

    #pragma unroll 1
    for (int ch = 0; ch < 16; ch++) {
        // stage weight slice wT[ch*4 .. ch*4+3][*][*] (contiguous 2304 floats)
        const float* wsrc = g_wT + ch * 2304;
        for (int s2 = t; s2 < 2304; s2 += 256) ws[s2] = wsrc[s2];

        // gather xoff for 4 channels of this chunk
        const float* xb = g_xpad + ch * 4;
        for (int s = t; s < 576; s += 256) {
            int4 id  = smidx[s];
            float4 wv = smw[s];
            float4 v0 = *(const float4*)(xb + id.x);
            float4 v1 = *(const float4*)(xb + id.y);
            float4 v2 = *(const float4*)(xb + id.z);
            float4 v3 = *(const float4*)(xb + id.w);
            float4 xo;
            xo.x = wv.x * v0.x + wv.y * v1.x + wv.z * v2.x + wv.w * v3.x;
            xo.y = wv.x * v0.y + wv.y * v1.y + wv.z * v2.y + wv.w * v3.y;
            xo.z = wv.x * v0.z + wv.y * v1.z + wv.z * v2.z + wv.w * v3.z;
            xo.w = wv.x * v0.w + wv.y * v1.w + wv.z * v2.w + wv.w * v3.w;
            int pix = s / 9;
            int n = s - pix * 9;
            int oidx = n * 64 + pix;
            xoffs[oidx]        = xo.x;
            xoffs[576 + oidx]  = xo.y;
            xoffs[1152 + oidx] = xo.z;
            xoffs[1728 + oidx] = xo.w;
        }
        __syncthreads();

        // GEMM: acc[o][pixpair] += w[o,cc,n] * xoff[cc,n,pix]
        #pragma unroll
        for (int cc = 0; cc < 4; cc++) {
            #pragma unroll
            for (int n = 0; n < 9; n++) {
                const ulonglong2 xu = *(const ulonglong2*)&xoffs[(cc * 9 + n) * 64 + pix0];
                const float4 wv = *(const float4*)&ws[(cc * 9 + n) * 64 + o0];
                ULL w0 = pack2(wv.x, wv.x);
                ULL w1 = pack2(wv.y, wv.y);
                ULL w2 = pack2(wv.z, wv.z);
                ULL w3 = pack2(wv.w, wv.w);
                acc[0][0] = ffma2(xu.x, w0, acc[0][0]); acc[0][1] = ffma2(xu.y, w0, acc[0][1]);
                acc[1][0] = ffma2(xu.x, w1, acc[1][0]); acc[1][1] = ffma2(xu.y, w1, acc[1][1]);
                acc[2][0] = ffma2(xu.x, w2, acc[2][0]); acc[2][1] = ffma2(xu.y, w2, acc[2][1]);
                acc[3][0] = ffma2(xu.x, w3, acc[3][0]); acc[3][1] = ffma2(xu.y, w3, acc[3][1]);
            }
        }
        __syncthreads();
    }

    int obase = ((b * O + o0) * H + i) * W + jt * 64 + pix0;
    #pragma unroll
    for (int k = 0; k < 4; k++) {
        float4 r;
        unpack2(acc[k][0], r.x, r.y);
        unpack2(acc[k][1], r.z, r.w);
        *(float4*)(out + obase + k * (H * W)) = r;
    }
}

// ============================================================================
extern "C" void kernel_launch(void* const* d_in, const int* in_sizes, int n_in,
                              void* d_out, int out_size) {
    const float* x0     = (const float*)d_in[0];
    const float* x1     = (const float*)d_in[1];
    const float* p_w    = (const float*)d_in[2];
    const float* p_b    = (const float*)d_in[3];
    const float* conv_w = (const float*)d_in[4];
    float* out = (float*)d_out;

    k_pad_transpose<<<B * 529, 256>>>(x0);
    k_prep_w<<<(O * C * N9 + 255) / 256, 256>>>(conv_w, p_w);
    k_offset_meta<<<(B * H * W) / 256, 256>>>(x1, p_b);
    k_main<<<B * H * 2, 256>>>(out);
}

// round 2
// speedup vs baseline: 1.3134x; 1.3134x over previous
#include <cuda_runtime.h>

typedef unsigned long long ULL;

// ---------------- constants ----------------
constexpr int B  = 4;
constexpr int C  = 64;
constexpr int H  = 128;
constexpr int W  = 128;
constexpr int Hp = 130;
constexpr int Wp = 130;
constexpr int O  = 64;
constexpr int N9 = 9;

// ---------------- scratch (device globals; no allocs) ----------------
__device__ __align__(16) float g_xpad[B * Hp * Wp * C];   // NHWC zero-padded x0
__device__ __align__(16) ULL   g_wTn2[N9 * C * O];        // [n][c][o] -> (w, w) duplicated f32 pair
__device__ __align__(16) ULL   g_pw2[N9 * C * N9];        // paired offset-conv weights
__device__ __align__(16) int4   g_midx[B * H * W * N9];   // 4 corner element-offsets into g_xpad
__device__ __align__(16) float4 g_mw[B * H * W * N9];     // 4 bilinear weights (lt, rb, lb, rt)

// ---------------- packed f32x2 helpers ----------------
__device__ __forceinline__ ULL ffma2(ULL a, ULL b, ULL c) {
    ULL d;
    asm("fma.rn.f32x2 %0, %1, %2, %3;" : "=l"(d) : "l"(a), "l"(b), "l"(c));
    return d;
}
__device__ __forceinline__ ULL pack2(float lo, float hi) {
    ULL d;
    asm("mov.b64 %0, {%1, %2};" : "=l"(d) : "f"(lo), "f"(hi));
    return d;
}
__device__ __forceinline__ void unpack2(ULL v, float& lo, float& hi) {
    asm("mov.b64 {%0, %1}, %2;" : "=f"(lo), "=f"(hi) : "l"(v));
}

// ============================================================================
// K1: pad + NCHW->NHWC transpose of x0 into g_xpad.
// ============================================================================
__global__ void __launch_bounds__(256) k_pad_transpose(const float* __restrict__ x0) {
    __shared__ float tile[64][33];
    int bp = blockIdx.x;                 // B * 529 blocks
    int b  = bp / 529;
    int p0 = (bp - b * 529) * 32;
    int tx = threadIdx.x & 31;
    int ty = threadIdx.x >> 5;

    #pragma unroll
    for (int cc = ty; cc < 64; cc += 8) {
        int p = p0 + tx;
        float v = 0.f;
        if (p < Hp * Wp) {
            int y = p / Wp, x = p - (p / Wp) * Wp;
            if (y >= 1 && y <= H && x >= 1 && x <= W)
                v = x0[((b * C + cc) * H + (y - 1)) * W + (x - 1)];
        }
        tile[cc][tx] = v;
    }
    __syncthreads();

    int base = (b * Hp * Wp + p0) * 64;
    for (int e = threadIdx.x; e < 32 * 64; e += 256) {
        int pl = e >> 6, c = e & 63;
        if (p0 + pl < Hp * Wp)
            g_xpad[base + pl * 64 + c] = tile[c][pl];
    }
}

// ============================================================================
// K1b: weight reshuffles.
//   g_wTn2[n][c][o] = pair( conv_w[o][c][n], same )
//   g_pw2[n][c][kk] = pair( p_w[n][c][kk], p_w[n+9][c][kk] )
// ============================================================================
__global__ void k_prep_w(const float* __restrict__ conv_w, const float* __restrict__ p_w) {
    int t = blockIdx.x * 256 + threadIdx.x;
    if (t < O * C * N9) {
        int o = t / (C * N9);
        int c = (t / N9) % C;
        int n = t % N9;
        float w = conv_w[t];
        g_wTn2[(n * C + c) * O + o] = pack2(w, w);
    }
    if (t < N9 * C * N9) {
        int n = t / (C * N9);
        int c = (t / N9) % C;
        int kk = t % N9;
        float wx = p_w[(n * C + c) * N9 + kk];
        float wy = p_w[((n + 9) * C + c) * N9 + kk];
        g_pw2[(n * C + c) * N9 + kk] = pack2(wx, wy);
    }
}

// ============================================================================
// K2: offset conv (3x3, pad 1, 18 out ch) fused with bilinear metadata.
// ============================================================================
__global__ void __launch_bounds__(256) k_offset_meta(const float* __restrict__ x1,
                                                     const float* __restrict__ p_b) {
    __shared__ ULL wsm[N9 * C * N9];   // 41472 bytes
    int t = threadIdx.x;
    for (int k = t; k < N9 * C * N9; k += 256) wsm[k] = g_pw2[k];
    __syncthreads();

    int P = blockIdx.x * 256 + t;          // 65536 pixels
    int b = P >> 14;
    int rem = P & 16383;
    int i = rem >> 7;
    int j = rem & 127;

    ULL acc[9];
    #pragma unroll
    for (int n = 0; n < 9; n++) acc[n] = pack2(p_b[n], p_b[n + 9]);

    const float* x1b = x1 + (b * C * H * W) + i * W + j;
    bool rok0 = (i > 0), rok2 = (i < H - 1), cok0 = (j > 0), cok2 = (j < W - 1);

    #pragma unroll 1
    for (int c = 0; c < C; c++) {
        const float* xc = x1b + c * (H * W);
        float v[9];
        #pragma unroll
        for (int di = 0; di < 3; di++) {
            bool rok = (di == 0) ? rok0 : ((di == 2) ? rok2 : true);
            const float* xr = xc + (di - 1) * W;
            v[di * 3 + 0] = (rok && cok0) ? xr[-1] : 0.f;
            v[di * 3 + 1] = rok ? xr[0] : 0.f;
            v[di * 3 + 2] = (rok && cok2) ? xr[1] : 0.f;
        }
        ULL vd[9];
        #pragma unroll
        for (int k = 0; k < 9; k++) vd[k] = pack2(v[k], v[k]);
        const ULL* wrow = &wsm[c * N9];
        #pragma unroll
        for (int n = 0; n < 9; n++) {
            const ULL* wn = wrow + n * (C * N9);
            #pragma unroll
            for (int k = 0; k < 9; k++)
                acc[n] = ffma2(vd[k], wn[k], acc[n]);
        }
    }

    int gs = P * 9;
    int xb130 = b * 130;
    #pragma unroll
    for (int n = 0; n < 9; n++) {
        float ox, oy;
        unpack2(acc[n], ox, oy);
        float px = (float)(i + n / 3) + ox;
        float py = (float)(j + n % 3) + oy;
        float fx = floorf(px), fy = floorf(py);
        int qltx = max(min((int)fx, Hp - 1), 0);
        int qlty = max(min((int)fy, Wp - 1), 0);
        int qrbx = max(min((int)fx + 1, Hp - 1), 0);
        int qrby = max(min((int)fy + 1, Wp - 1), 0);
        float pxc = fminf(fmaxf(px, 0.f), (float)(Hp - 1));
        float pyc = fminf(fmaxf(py, 0.f), (float)(Wp - 1));
        float ax = 1.f + (float)qltx - pxc;
        float bx = 1.f - (float)qrbx + pxc;
        float ay = 1.f + (float)qlty - pyc;
        float by = 1.f - (float)qrby + pyc;
        int4 idx;
        idx.x = ((xb130 + qltx) * 130 + qlty) * 64;   // lt
        idx.y = ((xb130 + qrbx) * 130 + qrby) * 64;   // rb
        idx.z = ((xb130 + qltx) * 130 + qrby) * 64;   // lb
        idx.w = ((xb130 + qrbx) * 130 + qlty) * 64;   // rt
        float4 wv;
        wv.x = ax * ay;  // g_lt
        wv.y = bx * by;  // g_rb
        wv.z = ax * by;  // g_lb
        wv.w = bx * ay;  // g_rt
        g_midx[gs + n] = idx;
        g_mw[gs + n] = wv;
    }
}

// ============================================================================
// K3: tap-major gather + reduction GEMM.
// Block = 64 pixels (half row) x 64 outputs, 256 threads.
// Per tap n: stage dup'd weight slice (32KB), coalesced-gather all 64 channels
// of 4 corners, blend in regs, transpose-store into swizzled xoff[c][pix],
// then 64 k-step FFMA2 GEMM (4o x 4pix per thread, zero MOV-dups).
// ============================================================================
__global__ void __launch_bounds__(256) k_main(float* __restrict__ out) {
    extern __shared__ char dsm[];
    ULL*   ws2   = (ULL*)dsm;               // 32768 B : [c][o] duplicated pairs
    char*  xoffb = dsm + 32768;             // 16384 B : [c][64 pix], quad-swizzled

    int t = threadIdx.x;
    int bid = blockIdx.x;                   // 1024 blocks
    int jt = bid & 1;
    int i  = (bid >> 1) & 127;
    int b  = bid >> 8;
    int pixbase = ((b * H + i) * W + jt * 64);

    int lg = t & 15;     // gather: channel-quad ; GEMM: pixel-quad
    int hg = t >> 4;     // gather: pixel-quad   ; GEMM: output-quad

    ULL acc[4][2];
    #pragma unroll
    for (int k = 0; k < 4; k++) { acc[k][0] = 0ull; acc[k][1] = 0ull; }

    const int4*   midx = g_midx + pixbase * 9;
    const float4* mw   = g_mw   + pixbase * 9;
    const float*  xb   = g_xpad + lg * 4;

    #pragma unroll 1
    for (int n = 0; n < 9; n++) {
        __syncthreads();   // previous GEMM readers done before overwrite

        // ---- stage duplicated weight slice for tap n (32 KB) ----
        {
            const ulonglong2* wsrc = (const ulonglong2*)(g_wTn2 + n * (C * O));
            ulonglong2* wdst = (ulonglong2*)ws2;
            #pragma unroll
            for (int k = 0; k < 8; k++) wdst[t + k * 256] = wsrc[t + k * 256];
        }

        // ---- gather + blend (thread: channels lg*4..+3, pixels hg*4..+3) ----
        float rr[4][4];   // [pixel-in-quad][channel-in-quad]
        #pragma unroll
        for (int pp = 0; pp < 4; pp++) {
            int pix = hg * 4 + pp;
            int4   id = midx[pix * 9 + n];
            float4 g  = mw[pix * 9 + n];
            float4 v0 = *(const float4*)(xb + id.x);
            float4 v1 = *(const float4*)(xb + id.y);
            float4 v2 = *(const float4*)(xb + id.z);
            float4 v3 = *(const float4*)(xb + id.w);
            rr[pp][0] = g.x * v0.x + g.y * v1.x + g.z * v2.x + g.w * v3.x;
            rr[pp][1] = g.x * v0.y + g.y * v1.y + g.z * v2.y + g.w * v3.y;
            rr[pp][2] = g.x * v0.z + g.y * v1.z + g.z * v2.z + g.w * v3.z;
            rr[pp][3] = g.x * v0.w + g.y * v1.w + g.z * v2.w + g.w * v3.w;
        }
        // transpose-store: channel c = lg*4+k, pixel-quad hg at swizzled slot hg^lg
        int sw = ((hg ^ lg) & 15) << 4;
        #pragma unroll
        for (int k = 0; k < 4; k++) {
            float4 sv = make_float4(rr[0][k], rr[1][k], rr[2][k], rr[3][k]);
            *(float4*)(xoffb + ((lg * 4 + k) << 8) + sw) = sv;
        }
        __syncthreads();

        // ---- GEMM: acc[o in hg*4..+3][pix in lg*4..+3] += w[o,c] * x[c,pix] ----
        #pragma unroll 1
        for (int cq = 0; cq < 16; cq++) {
            const char* xrow = xoffb + (cq << 10) + (((lg ^ cq) & 15) << 4);
            const ULL*  wrow = ws2 + (cq << 8) + hg * 4;
            #pragma unroll
            for (int j = 0; j < 4; j++) {
                ulonglong2 xu = *(const ulonglong2*)(xrow + (j << 8));
                ulonglong2 wa = *(const ulonglong2*)(wrow + j * 64);
                ulonglong2 wb = *(const ulonglong2*)(wrow + j * 64 + 2);
                acc[0][0] = ffma2(xu.x, wa.x, acc[0][0]); acc[0][1] = ffma2(xu.y, wa.x, acc[0][1]);
                acc[1][0] = ffma2(xu.x, wa.y, acc[1][0]); acc[1][1] = ffma2(xu.y, wa.y, acc[1][1]);
                acc[2][0] = ffma2(xu.x, wb.x, acc[2][0]); acc[2][1] = ffma2(xu.y, wb.x, acc[2][1]);
                acc[3][0] = ffma2(xu.x, wb.y, acc[3][0]); acc[3][1] = ffma2(xu.y, wb.y, acc[3][1]);
            }
        }
    }

    // ---- write out: o = hg*4+k, pixels lg*4..+3 (coalesced across lg) ----
    int obase = ((b * O + hg * 4) * H + i) * W + jt * 64 + lg * 4;
    #pragma unroll
    for (int k = 0; k < 4; k++) {
        float4 r;
        unpack2(acc[k][0], r.x, r.y);
        unpack2(acc[k][1], r.z, r.w);
        *(float4*)(out + obase + k * (H * W)) = r;
    }
}

// ============================================================================
extern "C" void kernel_launch(void* const* d_in, const int* in_sizes, int n_in,
                              void* d_out, int out_size) {
    const float* x0     = (const float*)d_in[0];
    const float* x1     = (const float*)d_in[1];
    const float* p_w    = (const float*)d_in[2];
    const float* p_b    = (const float*)d_in[3];
    const float* conv_w = (const float*)d_in[4];
    float* out = (float*)d_out;

    static_assert(sizeof(ULL) == 8, "");
    cudaFuncSetAttribute(k_main, cudaFuncAttributeMaxDynamicSharedMemorySize, 49152);

    k_pad_transpose<<<B * 529, 256>>>(x0);
    k_prep_w<<<(O * C * N9 + 255) / 256, 256>>>(conv_w, p_w);
    k_offset_meta<<<(B * H * W) / 256, 256>>>(x1, p_b);
    k_main<<<B * H * 2, 256, 49152>>>(out);
}